// round 14
// baseline (speedup 1.0000x reference)
#include <cuda_runtime.h>
#include <cstdint>

#define NJ 50
#define NJP 56
#define EDIM 192
#define NTHREADS 256
#define ROWS_PER_BLOCK 256
#define EBS 56            // Eb row stride (u32): Eb[k][j]
#define XRF 20            // xs row stride in floats (16 + 4 pad)
#define STAGEF 5120       // floats per stage (256 rows * 20)
#define NCHUNK 12         // 12 chunks of 16 k

// dynamic smem byte offsets
#define OFF_EB   0                       // 192*56*4 = 43008
#define OFF_XS   43008                   // 3 stages * 20480 = 61440
#define OFF_SXX  104448                  // 256*4
#define OFF_SEE  105472                  // 56*4
#define OFF_SB   105696                  // 56*4
#define OFF_BJ   105920                  // 256*4
#define OFF_CM   106944                  // 256*8 candidate masks
#define OFF_WRED 108992                  // 8*4
#define SMEM_TOTAL 109024                // 2 CTAs/SM (218 KB <= 228 KB)

__device__ double g_loss_sum;    // zero-init at load
__device__ unsigned int g_done;

#define CVT_TF32(u, f) asm("cvt.rna.tf32.f32 %0, %1;" : "=r"(u) : "f"(f))
#define MMA_TF32(d, a0, a1, a2, a3, b0, b1) \
    asm volatile("mma.sync.aligned.m16n8k8.row.col.f32.tf32.tf32.f32 " \
        "{%0,%1,%2,%3}, {%4,%5,%6,%7}, {%8,%9}, {%0,%1,%2,%3};" \
        : "+f"((d)[0]), "+f"((d)[1]), "+f"((d)[2]), "+f"((d)[3]) \
        : "r"(a0), "r"(a1), "r"(a2), "r"(a3), "r"(b0), "r"(b1))
#define CP_COMMIT() asm volatile("cp.async.commit_group;" ::: "memory")
#define CP_WAIT1()  asm volatile("cp.async.wait_group 1;" ::: "memory")

static __device__ __forceinline__ void cp16(uint32_t dst, const void* src) {
    asm volatile("cp.async.ca.shared.global [%0], [%1], 16;" :: "r"(dst), "l"(src));
}
static __device__ __forceinline__ uint32_t smem_u32(const void* p) {
    uint32_t a;
    asm("{ .reg .u64 t; cvta.to.shared.u64 t, %1; cvt.u32.u64 %0, t; }" : "=r"(a) : "l"(p));
    return a;
}

// Exact m for (row x, code j): bit-identical to the R2/R5/R6/R9/R12/R13 passing chain.
static __device__ __forceinline__ float exact_m(const float4* xrow, const float4* e4,
                                                int j, float sxx, const float* see) {
    float dd = 0.f;
    const float4* ej = e4 + (size_t)j * 48;
    #pragma unroll 4
    for (int k0 = 0; k0 < 48; ++k0) {
        const float4 xv = __ldg(xrow + k0);
        const float4 ev = __ldg(ej + k0);
        dd = fmaf(xv.x, ev.x, dd); dd = fmaf(xv.y, ev.y, dd);
        dd = fmaf(xv.z, ev.z, dd); dd = fmaf(xv.w, ev.w, dd);
    }
    return __fsub_rn(__fadd_rn(sxx, see[j]), 2.0f * dd);
}

__global__ void __launch_bounds__(NTHREADS, 2) vq_kernel(
        const float* __restrict__ x, const float* __restrict__ e,
        float* __restrict__ out, int n) {
    extern __shared__ __align__(16) char smem[];
    uint32_t* Eb     = (uint32_t*)(smem + OFF_EB);
    float*    xsf    = (float*)(smem + OFF_XS);
    float*    sxx_sh = (float*)(smem + OFF_SXX);
    float*    see    = (float*)(smem + OFF_SEE);
    float*    sB     = (float*)(smem + OFF_SB);
    int*      bjsh   = (int*)(smem + OFF_BJ);
    unsigned long long* cmask = (unsigned long long*)(smem + OFF_CM);
    float*    wred   = (float*)(smem + OFF_WRED);

    const int tid = threadIdx.x;
    const int wid = tid >> 5;
    const int lane = tid & 31;
    const int gid = lane >> 2;       // 0..7
    const int tig = lane & 3;        // 0..3

    const int tile_base = blockIdx.x * ROWS_PER_BLOCK;
    const float4* x4 = reinterpret_cast<const float4*>(x);
    const float4* e4 = reinterpret_cast<const float4*>(e);
    const uint32_t xs_sa = smem_u32(smem + OFF_XS);

    // ---- stage helper (4 cp.async of 16B per thread per chunk) ----
    auto stage = [&](int c) {
        const uint32_t dstb = xs_sa + (uint32_t)(c % 3) * (STAGEF * 4);
        #pragma unroll
        for (int i = 0; i < 4; ++i) {
            const int idx = tid + i * NTHREADS;
            const int row = idx >> 2, kql = idx & 3;
            int gr = tile_base + row; if (gr >= n) gr = n - 1;
            cp16(dstb + (uint32_t)(row * XRF + kql * 4) * 4,
                 x4 + (size_t)gr * 48 + c * 4 + kql);
        }
        CP_COMMIT();
    };

    // ---- prologue: kick chunks 0,1 while doing init work ----
    stage(0);
    stage(1);

    // ---- init: Eb (tf32), see exact chain, bound coeffs ----
    for (int i = tid; i < EDIM * EBS; i += NTHREADS) Eb[i] = 0u;
    __syncthreads();
    for (int i = tid; i < NJ * EDIM; i += NTHREADS) {
        int j = i / EDIM, k = i - j * EDIM;
        uint32_t u; CVT_TF32(u, __ldg(e + i));
        Eb[k * EBS + j] = u;
    }
    if (tid < NJP) {
        float s = 1e38f;
        if (tid < NJ) {
            s = 0.f;
            const float* ej = e + (size_t)tid * EDIM;
            #pragma unroll 4
            for (int k = 0; k < EDIM; ++k) { float v = __ldg(ej + k); s = fmaf(v, v, s); }
        }
        see[tid] = s;
        sB[tid] = (tid < NJ) ? 2.4e-3f * sqrtf(s) : 0.f;
    }

    float d2[2][7][4];
    #pragma unroll
    for (int t2 = 0; t2 < 2; ++t2)
        #pragma unroll
        for (int nt = 0; nt < 7; ++nt)
            #pragma unroll
            for (int q = 0; q < 4; ++q) d2[t2][nt][q] = 0.f;
    float s0 = 0.f, s1 = 0.f;        // ||x||^2 partials for row 'tid' (R2 chain order)

    // ---- main pipelined loop: 12 chunks of 16 k ----
    #pragma unroll 1
    for (int c = 0; c < NCHUNK; ++c) {
        CP_WAIT1();                  // chunk c landed (c+1 may be in flight)
        __syncthreads();
        if (c + 2 < NCHUNK) stage(c + 2);

        const float* xb = xsf + (c % 3) * STAGEF;
        {                            // exact ||x||^2 partials, k ascending
            const float4* xr = (const float4*)(xb + tid * XRF);
            #pragma unroll
            for (int q = 0; q < 4; ++q) {
                const float4 v = xr[q];
                s0 = fmaf(v.x, v.x, s0); s1 = fmaf(v.y, v.y, s1);
                s0 = fmaf(v.z, v.z, s0); s1 = fmaf(v.w, v.w, s1);
            }
        }
        const int arow = wid * 16 + gid;
        #pragma unroll
        for (int kt = 0; kt < 2; ++kt) {
            const int c0 = kt * 8 + tig;
            uint32_t a0, a1, a2, a3, a4, a5, a6, a7;
            CVT_TF32(a0, xb[arow * XRF + c0]);
            CVT_TF32(a1, xb[(arow + 8) * XRF + c0]);
            CVT_TF32(a2, xb[arow * XRF + c0 + 4]);
            CVT_TF32(a3, xb[(arow + 8) * XRF + c0 + 4]);
            CVT_TF32(a4, xb[(arow + 128) * XRF + c0]);
            CVT_TF32(a5, xb[(arow + 136) * XRF + c0]);
            CVT_TF32(a6, xb[(arow + 128) * XRF + c0 + 4]);
            CVT_TF32(a7, xb[(arow + 136) * XRF + c0 + 4]);
            const int kg = c * 16 + kt * 8 + tig;
            const uint32_t* eb0 = Eb + (size_t)kg * EBS + gid;
            const uint32_t* eb1 = Eb + (size_t)(kg + 4) * EBS + gid;
            #pragma unroll
            for (int nt = 0; nt < 7; ++nt) {
                const uint32_t b0 = eb0[nt * 8];
                const uint32_t b1 = eb1[nt * 8];
                MMA_TF32(d2[0][nt], a0, a1, a2, a3, b0, b1);
                MMA_TF32(d2[1][nt], a4, a5, a6, a7, b0, b1);
            }
        }
    }
    sxx_sh[tid] = s0 + s1;
    __syncthreads();

    // ---- screen: rigorous candidate mask from tf32 dots ----
    #pragma unroll
    for (int t2 = 0; t2 < 2; ++t2)
    #pragma unroll
    for (int half = 0; half < 2; ++half) {
        const int row = t2 * 128 + wid * 16 + gid + half * 8;
        const float sxx = sxx_sh[row];
        const float sqxx = sqrtf(sxx);
        float R = 3.402823466e38f;
        #pragma unroll
        for (int nt = 0; nt < 7; ++nt)
            #pragma unroll
            for (int c2 = 0; c2 < 2; ++c2) {
                const int j = nt * 8 + 2 * tig + c2;
                const float dv = d2[t2][nt][half * 2 + c2];
                const float m = __fsub_rn(__fadd_rn(sxx, see[j]), 2.0f * dv);
                const float Bv = fmaf(sqxx, sB[j], 3e-4f);
                R = fminf(R, m + Bv);
            }
        R = fminf(R, __shfl_xor_sync(0xffffffffu, R, 1));
        R = fminf(R, __shfl_xor_sync(0xffffffffu, R, 2));
        unsigned long long lm = 0ull;
        #pragma unroll
        for (int nt = 0; nt < 7; ++nt)
            #pragma unroll
            for (int c2 = 0; c2 < 2; ++c2) {
                const int j = nt * 8 + 2 * tig + c2;
                const float dv = d2[t2][nt][half * 2 + c2];
                const float m = __fsub_rn(__fadd_rn(sxx, see[j]), 2.0f * dv);
                const float Bv = fmaf(sqxx, sB[j], 3e-4f);
                if (m - Bv <= R) lm |= 1ull << j;
            }
        lm |= __shfl_xor_sync(0xffffffffu, lm, 1);
        lm |= __shfl_xor_sync(0xffffffffu, lm, 2);
        if (tig == 0) {
            cmask[row] = lm;
            bjsh[row] = (__popcll(lm) == 1) ? (__ffsll(lm) - 1) : -1;
        }
    }
    __syncthreads();

    // ---- rescue: one thread per row, exact chain over candidates (ascending j) ----
    {
        const int r = tid;
        int bj = bjsh[r];
        if (bj < 0) {
            int gr = tile_base + r; if (gr >= n) gr = n - 1;
            const float4* xr = x4 + (size_t)gr * 48;
            const float sxx = sxx_sh[r];
            unsigned long long m2 = cmask[r];
            float bv = 3.402823466e38f; bj = 0;
            while (m2) {
                const int j = __ffsll(m2) - 1; m2 &= m2 - 1;
                const float m = exact_m(xr, e4, j, sxx, see);
                if (m < bv) { bv = m; bj = j; }   // ascending j => first-index ties
            }
            bjsh[r] = bj;
        }
        const int grow = tile_base + r;
        if (grow < n) out[(size_t)n * EDIM + grow] = (float)bj;
    }
    __syncthreads();

    // ---- phase 2: coalesced straight-through write + loss ----
    float lsum = 0.f;
    float4* o4 = reinterpret_cast<float4*>(out);
    #pragma unroll 4
    for (int it = 0; it < 48; ++it) {                 // 32 rows * 48 f4 / 32 lanes
        const int idx = it * 32 + lane;
        const int rl = idx / 48, c4 = idx - rl * 48;
        const int row = (rl >> 4) * 128 + wid * 16 + (rl & 15);
        const int grow = tile_base + row;
        if (grow < n) {
            const int bj = bjsh[row];
            const float4 xq = __ldg(x4 + (size_t)grow * 48 + c4);
            const float4 qq = __ldg(e4 + (size_t)bj * 48 + c4);
            float dx = __fsub_rn(qq.x, xq.x), dy = __fsub_rn(qq.y, xq.y);
            float dz = __fsub_rn(qq.z, xq.z), dw = __fsub_rn(qq.w, xq.w);
            lsum = fmaf(dx, dx, lsum); lsum = fmaf(dy, dy, lsum);
            lsum = fmaf(dz, dz, lsum); lsum = fmaf(dw, dw, lsum);
            float4 o;
            o.x = __fadd_rn(xq.x, dx); o.y = __fadd_rn(xq.y, dy);
            o.z = __fadd_rn(xq.z, dz); o.w = __fadd_rn(xq.w, dw);
            o4[(size_t)grow * 48 + c4] = o;
        }
    }

    // ---- loss reduction + single-kernel finalize ----
    #pragma unroll
    for (int off = 16; off > 0; off >>= 1)
        lsum += __shfl_down_sync(0xffffffffu, lsum, off);
    if (lane == 0) wred[wid] = lsum;
    __syncthreads();
    if (tid == 0) {
        float bs = 0.f;
        #pragma unroll
        for (int w = 0; w < 8; ++w) bs += wred[w];
        atomicAdd(&g_loss_sum, (double)bs);
        __threadfence();
        unsigned int prev = atomicAdd(&g_done, 1u);
        if (prev == gridDim.x - 1) {
            __threadfence();
            double total = atomicAdd(&g_loss_sum, 0.0);
            double mean = total / ((double)n * (double)EDIM);
            out[(size_t)n * EDIM + n]     = (float)(1.25 * mean);  // (1+BETA)*mean
            out[(size_t)n * EDIM + n + 1] = 0.0f;                  // contrastloss
            g_loss_sum = 0.0;
            g_done = 0u;
            __threadfence();
        }
    }
}

extern "C" void kernel_launch(void* const* d_in, const int* in_sizes, int n_in,
                              void* d_out, int out_size) {
    (void)n_in; (void)out_size;
    const float* x = (const float*)d_in[0];   // [N, 192] fp32
    const float* e = (const float*)d_in[1];   // [50, 192] fp32
    float* out = (float*)d_out;               // [N*192 | N | 1 | 1] fp32
    const int n = in_sizes[0] / EDIM;

    static int configured = 0;
    if (!configured) {
        cudaFuncSetAttribute(vq_kernel, cudaFuncAttributeMaxDynamicSharedMemorySize,
                             SMEM_TOTAL);
        configured = 1;
    }
    const int blocks = (n + ROWS_PER_BLOCK - 1) / ROWS_PER_BLOCK;
    vq_kernel<<<blocks, NTHREADS, SMEM_TOTAL>>>(x, e, out, n);
}

// round 15
// speedup vs baseline: 1.0676x; 1.0676x over previous
#include <cuda_runtime.h>
#include <cstdint>

#define NJ 50
#define NJP 56
#define EDIM 192
#define NTHREADS 256
#define ROWS_PER_BLOCK 256
#define EBS 56            // Eb row stride (u32): Eb[k][j]
#define NCHUNK 6          // 6 chunks of 32 k

// dynamic smem byte offsets
#define OFF_EB   0                       // 192*56*4 = 43008
#define OFF_XW   43008                   // 8 warps * 2 stages * 32 rows * 128 B = 65536
#define OFF_SXX  108544                  // 256*4
#define OFF_SEE  109568                  // 56*4
#define OFF_SB   109792                  // 56*4
#define OFF_BJ   110016                  // 256*4
#define OFF_CM   111040                  // 256*8 candidate masks
#define OFF_WRED 113088                  // 8*4
#define SMEM_TOTAL 113120                // 2 CTAs/SM (226 KB + reserve <= 228 KB)

__device__ double g_loss_sum;    // zero-init at load
__device__ unsigned int g_done;

#define CVT_TF32(u, f) asm("cvt.rna.tf32.f32 %0, %1;" : "=r"(u) : "f"(f))
#define MMA_TF32(d, a0, a1, a2, a3, b0, b1) \
    asm volatile("mma.sync.aligned.m16n8k8.row.col.f32.tf32.tf32.f32 " \
        "{%0,%1,%2,%3}, {%4,%5,%6,%7}, {%8,%9}, {%0,%1,%2,%3};" \
        : "+f"((d)[0]), "+f"((d)[1]), "+f"((d)[2]), "+f"((d)[3]) \
        : "r"(a0), "r"(a1), "r"(a2), "r"(a3), "r"(b0), "r"(b1))
#define CP_COMMIT() asm volatile("cp.async.commit_group;" ::: "memory")
#define CP_WAIT1()  asm volatile("cp.async.wait_group 1;" ::: "memory")
#define CP_WAIT0()  asm volatile("cp.async.wait_group 0;" ::: "memory")

static __device__ __forceinline__ void cp16(uint32_t dst, const void* src) {
    asm volatile("cp.async.ca.shared.global [%0], [%1], 16;" :: "r"(dst), "l"(src));
}
static __device__ __forceinline__ uint32_t smem_u32(const void* p) {
    uint32_t a;
    asm("{ .reg .u64 t; cvta.to.shared.u64 t, %1; cvt.u32.u64 %0, t; }" : "=r"(a) : "l"(p));
    return a;
}

// Exact m for (row x, code j): bit-identical to the R2..R14 passing chain.
static __device__ __forceinline__ float exact_m(const float4* xrow, const float4* e4,
                                                int j, float sxx, const float* see) {
    float dd = 0.f;
    const float4* ej = e4 + (size_t)j * 48;
    #pragma unroll 4
    for (int k0 = 0; k0 < 48; ++k0) {
        const float4 xv = __ldg(xrow + k0);
        const float4 ev = __ldg(ej + k0);
        dd = fmaf(xv.x, ev.x, dd); dd = fmaf(xv.y, ev.y, dd);
        dd = fmaf(xv.z, ev.z, dd); dd = fmaf(xv.w, ev.w, dd);
    }
    return __fsub_rn(__fadd_rn(sxx, see[j]), 2.0f * dd);
}

__global__ void __launch_bounds__(NTHREADS, 2) vq_kernel(
        const float* __restrict__ x, const float* __restrict__ e,
        float* __restrict__ out, int n) {
    extern __shared__ __align__(16) char smem[];
    uint32_t* Eb     = (uint32_t*)(smem + OFF_EB);
    float*    sxx_sh = (float*)(smem + OFF_SXX);
    float*    see    = (float*)(smem + OFF_SEE);
    float*    sB     = (float*)(smem + OFF_SB);
    int*      bjsh   = (int*)(smem + OFF_BJ);
    unsigned long long* cmask = (unsigned long long*)(smem + OFF_CM);
    float*    wred   = (float*)(smem + OFF_WRED);

    const int tid = threadIdx.x;
    const int wid = tid >> 5;
    const int lane = tid & 31;
    const int gid = lane >> 2;       // 0..7
    const int tig = lane & 3;        // 0..3

    const int tile_base = blockIdx.x * ROWS_PER_BLOCK;
    const float4* x4 = reinterpret_cast<const float4*>(x);
    const float4* e4 = reinterpret_cast<const float4*>(e);
    const uint32_t xw_sa = smem_u32(smem + OFF_XW);

    // lane->block-row map for this warp's 32 rows (16 low + 16 at +128)
    const int myrow = (lane < 16) ? (wid * 16 + lane) : (112 + wid * 16 + lane);

    // ---- warp-private stage: 32 rows x 32 floats (128B/row), XOR-swizzled ----
    auto stage = [&](int c) {
        const uint32_t dstb = xw_sa + (uint32_t)((wid * 2 + (c & 1)) * 4096);
        #pragma unroll
        for (int i = 0; i < 8; ++i) {
            const int idx = lane + i * 32;
            const int r = idx >> 3;                    // buffer row 0..31
            const int g4 = idx & 7;                    // granule 0..7
            const int br = (r < 16) ? (wid * 16 + r) : (112 + wid * 16 + r);
            int gr = tile_base + br; if (gr >= n) gr = n - 1;
            const uint32_t dst = dstb + (uint32_t)(r * 128 + ((g4 ^ (r & 7)) << 4));
            cp16(dst, x4 + (size_t)gr * 48 + c * 8 + g4);
        }
        CP_COMMIT();
    };

    // ---- prologue: kick chunks 0,1 while initializing Eb/see ----
    stage(0);
    stage(1);

    for (int i = tid; i < EDIM * EBS; i += NTHREADS) Eb[i] = 0u;
    __syncthreads();
    for (int i = tid; i < NJ * EDIM; i += NTHREADS) {
        int j = i / EDIM, k = i - j * EDIM;
        uint32_t u; CVT_TF32(u, __ldg(e + i));
        Eb[k * EBS + j] = u;
    }
    if (tid < NJP) {
        float s = 1e38f;
        if (tid < NJ) {
            s = 0.f;
            const float* ej = e + (size_t)tid * EDIM;
            #pragma unroll 4
            for (int k = 0; k < EDIM; ++k) { float v = __ldg(ej + k); s = fmaf(v, v, s); }
        }
        see[tid] = s;
        sB[tid] = (tid < NJ) ? 2.4e-3f * sqrtf(s) : 0.f;
    }
    __syncthreads();                 // Eb/see visible; no more block barriers until loss

    float d2[2][7][4];
    #pragma unroll
    for (int t2 = 0; t2 < 2; ++t2)
        #pragma unroll
        for (int nt = 0; nt < 7; ++nt)
            #pragma unroll
            for (int q = 0; q < 4; ++q) d2[t2][nt][q] = 0.f;
    float s0 = 0.f, s1 = 0.f;        // ||x||^2 partials for this lane's row (R2 order)

    // ---- main loop: 6 chunks of 32 k, warp-private double buffer ----
    #pragma unroll 1
    for (int c = 0; c < NCHUNK; ++c) {
        if (c >= NCHUNK - 2) CP_WAIT0(); else CP_WAIT1();
        __syncwarp();
        const float* xb = (const float*)(smem + OFF_XW + (wid * 2 + (c & 1)) * 4096);

        {                            // sxx: lane 'lane' = buffer row 'lane', k ascending
            const float4* xr4 = (const float4*)xb;
            #pragma unroll
            for (int q = 0; q < 8; ++q) {
                const float4 v = xr4[lane * 8 + (q ^ (lane & 7))];
                s0 = fmaf(v.x, v.x, s0); s1 = fmaf(v.y, v.y, s1);
                s0 = fmaf(v.z, v.z, s0); s1 = fmaf(v.w, v.w, s1);
            }
        }
        #pragma unroll
        for (int kt = 0; kt < 4; ++kt) {
            const int gsw0 = (((2 * kt)     ^ gid) << 2) + tig;
            const int gsw1 = (((2 * kt + 1) ^ gid) << 2) + tig;
            const int r0 = gid * 32, r1 = (gid + 8) * 32;
            const int r2 = (gid + 16) * 32, r3 = (gid + 24) * 32;
            uint32_t a0, a1, a2, a3, a4, a5, a6, a7;
            CVT_TF32(a0, xb[r0 + gsw0]); CVT_TF32(a1, xb[r1 + gsw0]);
            CVT_TF32(a2, xb[r0 + gsw1]); CVT_TF32(a3, xb[r1 + gsw1]);
            CVT_TF32(a4, xb[r2 + gsw0]); CVT_TF32(a5, xb[r3 + gsw0]);
            CVT_TF32(a6, xb[r2 + gsw1]); CVT_TF32(a7, xb[r3 + gsw1]);
            const int kg = c * 32 + kt * 8 + tig;
            const uint32_t* eb0 = Eb + (size_t)kg * EBS + gid;
            const uint32_t* eb1 = Eb + (size_t)(kg + 4) * EBS + gid;
            #pragma unroll
            for (int nt = 0; nt < 7; ++nt) {
                const uint32_t b0 = eb0[nt * 8];
                const uint32_t b1 = eb1[nt * 8];
                MMA_TF32(d2[0][nt], a0, a1, a2, a3, b0, b1);
                MMA_TF32(d2[1][nt], a4, a5, a6, a7, b0, b1);
            }
        }
        __syncwarp();                // buffer c%2 fully consumed by this warp
        if (c + 2 < NCHUNK) stage(c + 2);
    }
    sxx_sh[myrow] = s0 + s1;
    __syncwarp();

    // ---- screen: rigorous candidate mask from tf32 dots (warp-local rows) ----
    #pragma unroll
    for (int t2 = 0; t2 < 2; ++t2)
    #pragma unroll
    for (int half = 0; half < 2; ++half) {
        const int row = t2 * 128 + wid * 16 + gid + half * 8;
        const float sxx = sxx_sh[row];
        const float sqxx = sqrtf(sxx);
        float R = 3.402823466e38f;
        #pragma unroll
        for (int nt = 0; nt < 7; ++nt)
            #pragma unroll
            for (int c2 = 0; c2 < 2; ++c2) {
                const int j = nt * 8 + 2 * tig + c2;
                const float dv = d2[t2][nt][half * 2 + c2];
                const float m = __fsub_rn(__fadd_rn(sxx, see[j]), 2.0f * dv);
                const float Bv = fmaf(sqxx, sB[j], 3e-4f);
                R = fminf(R, m + Bv);
            }
        R = fminf(R, __shfl_xor_sync(0xffffffffu, R, 1));
        R = fminf(R, __shfl_xor_sync(0xffffffffu, R, 2));
        unsigned long long lm = 0ull;
        #pragma unroll
        for (int nt = 0; nt < 7; ++nt)
            #pragma unroll
            for (int c2 = 0; c2 < 2; ++c2) {
                const int j = nt * 8 + 2 * tig + c2;
                const float dv = d2[t2][nt][half * 2 + c2];
                const float m = __fsub_rn(__fadd_rn(sxx, see[j]), 2.0f * dv);
                const float Bv = fmaf(sqxx, sB[j], 3e-4f);
                if (m - Bv <= R) lm |= 1ull << j;
            }
        lm |= __shfl_xor_sync(0xffffffffu, lm, 1);
        lm |= __shfl_xor_sync(0xffffffffu, lm, 2);
        if (tig == 0) {
            cmask[row] = lm;
            bjsh[row] = (__popcll(lm) == 1) ? (__ffsll(lm) - 1) : -1;
        }
    }
    __syncwarp();

    // ---- rescue: lane per own row, exact chain over candidates (ascending j) ----
    {
        const int r = myrow;
        int bj = bjsh[r];
        if (bj < 0) {
            int gr = tile_base + r; if (gr >= n) gr = n - 1;
            const float4* xr = x4 + (size_t)gr * 48;
            const float sxx = sxx_sh[r];
            unsigned long long m2 = cmask[r];
            float bv = 3.402823466e38f; bj = 0;
            while (m2) {
                const int j = __ffsll(m2) - 1; m2 &= m2 - 1;
                const float m = exact_m(xr, e4, j, sxx, see);
                if (m < bv) { bv = m; bj = j; }   // ascending j => first-index ties
            }
            bjsh[r] = bj;
        }
        const int grow = tile_base + r;
        if (grow < n) out[(size_t)n * EDIM + grow] = (float)bj;
    }
    __syncwarp();

    // ---- phase 2: coalesced straight-through write + loss (warp-local rows) ----
    float lsum = 0.f;
    float4* o4 = reinterpret_cast<float4*>(out);
    #pragma unroll 4
    for (int it = 0; it < 48; ++it) {                 // 32 rows * 48 f4 / 32 lanes
        const int idx = it * 32 + lane;
        const int rl = idx / 48, c4 = idx - rl * 48;
        const int row = (rl >> 4) * 128 + wid * 16 + (rl & 15);
        const int grow = tile_base + row;
        if (grow < n) {
            const int bj = bjsh[row];
            const float4 xq = __ldg(x4 + (size_t)grow * 48 + c4);
            const float4 qq = __ldg(e4 + (size_t)bj * 48 + c4);
            float dx = __fsub_rn(qq.x, xq.x), dy = __fsub_rn(qq.y, xq.y);
            float dz = __fsub_rn(qq.z, xq.z), dw = __fsub_rn(qq.w, xq.w);
            lsum = fmaf(dx, dx, lsum); lsum = fmaf(dy, dy, lsum);
            lsum = fmaf(dz, dz, lsum); lsum = fmaf(dw, dw, lsum);
            float4 o;
            o.x = __fadd_rn(xq.x, dx); o.y = __fadd_rn(xq.y, dy);
            o.z = __fadd_rn(xq.z, dz); o.w = __fadd_rn(xq.w, dw);
            o4[(size_t)grow * 48 + c4] = o;
        }
    }

    // ---- loss reduction + single-kernel finalize (only block barrier cluster) ----
    #pragma unroll
    for (int off = 16; off > 0; off >>= 1)
        lsum += __shfl_down_sync(0xffffffffu, lsum, off);
    if (lane == 0) wred[wid] = lsum;
    __syncthreads();
    if (tid == 0) {
        float bs = 0.f;
        #pragma unroll
        for (int w = 0; w < 8; ++w) bs += wred[w];
        atomicAdd(&g_loss_sum, (double)bs);
        __threadfence();
        unsigned int prev = atomicAdd(&g_done, 1u);
        if (prev == gridDim.x - 1) {
            __threadfence();
            double total = atomicAdd(&g_loss_sum, 0.0);
            double mean = total / ((double)n * (double)EDIM);
            out[(size_t)n * EDIM + n]     = (float)(1.25 * mean);  // (1+BETA)*mean
            out[(size_t)n * EDIM + n + 1] = 0.0f;                  // contrastloss
            g_loss_sum = 0.0;
            g_done = 0u;
            __threadfence();
        }
    }
}

extern "C" void kernel_launch(void* const* d_in, const int* in_sizes, int n_in,
                              void* d_out, int out_size) {
    (void)n_in; (void)out_size;
    const float* x = (const float*)d_in[0];   // [N, 192] fp32
    const float* e = (const float*)d_in[1];   // [50, 192] fp32
    float* out = (float*)d_out;               // [N*192 | N | 1 | 1] fp32
    const int n = in_sizes[0] / EDIM;

    static int configured = 0;
    if (!configured) {
        cudaFuncSetAttribute(vq_kernel, cudaFuncAttributeMaxDynamicSharedMemorySize,
                             SMEM_TOTAL);
        configured = 1;
    }
    const int blocks = (n + ROWS_PER_BLOCK - 1) / ROWS_PER_BLOCK;
    vq_kernel<<<blocks, NTHREADS, SMEM_TOTAL>>>(x, e, out, n);
}

// round 16
// speedup vs baseline: 1.1643x; 1.0906x over previous
#include <cuda_runtime.h>
#include <cstdint>

#define NJ 50
#define NJP 56
#define EDIM 192
#define NTHREADS 256
#define ROWS_PER_BLOCK 256
#define NCHUNK 6          // 6 chunks of 32 k

// dynamic smem byte offsets
#define OFF_EB   0                       // u64[24][56][4] = 43008
#define OFF_XS   43008                   // 2 bufs * 256 rows * 128 B = 65536
#define OFF_SXX  108544                  // 256*4
#define OFF_SEE  109568                  // 56*4
#define OFF_SB   109792                  // 56*4
#define OFF_BJ   110016                  // 256*4
#define OFF_CM   111040                  // 256*8 candidate masks
#define OFF_WRED 113088                  // 8*4
#define SMEM_TOTAL 113120                // 2 CTAs/SM (proven at this size in R15)

__device__ double g_loss_sum;    // zero-init at load
__device__ unsigned int g_done;

#define CVT_TF32(u, f) asm("cvt.rna.tf32.f32 %0, %1;" : "=r"(u) : "f"(f))
#define MMA_TF32(d, a0, a1, a2, a3, b0, b1) \
    asm volatile("mma.sync.aligned.m16n8k8.row.col.f32.tf32.tf32.f32 " \
        "{%0,%1,%2,%3}, {%4,%5,%6,%7}, {%8,%9}, {%0,%1,%2,%3};" \
        : "+f"((d)[0]), "+f"((d)[1]), "+f"((d)[2]), "+f"((d)[3]) \
        : "r"(a0), "r"(a1), "r"(a2), "r"(a3), "r"(b0), "r"(b1))
#define CP_COMMIT() asm volatile("cp.async.commit_group;" ::: "memory")
#define CP_WAIT1()  asm volatile("cp.async.wait_group 1;" ::: "memory")
#define CP_WAIT0()  asm volatile("cp.async.wait_group 0;" ::: "memory")

static __device__ __forceinline__ void cp16(uint32_t dst, const void* src) {
    asm volatile("cp.async.ca.shared.global [%0], [%1], 16;" :: "r"(dst), "l"(src));
}
static __device__ __forceinline__ uint32_t smem_u32(const void* p) {
    uint32_t a;
    asm("{ .reg .u64 t; cvta.to.shared.u64 t, %1; cvt.u32.u64 %0, t; }" : "=r"(a) : "l"(p));
    return a;
}

// Exact m for (row x, code j): bit-identical to the R2..R15 passing chain.
static __device__ __forceinline__ float exact_m(const float4* xrow, const float4* e4,
                                                int j, float sxx, const float* see) {
    float dd = 0.f;
    const float4* ej = e4 + (size_t)j * 48;
    #pragma unroll 4
    for (int k0 = 0; k0 < 48; ++k0) {
        const float4 xv = __ldg(xrow + k0);
        const float4 ev = __ldg(ej + k0);
        dd = fmaf(xv.x, ev.x, dd); dd = fmaf(xv.y, ev.y, dd);
        dd = fmaf(xv.z, ev.z, dd); dd = fmaf(xv.w, ev.w, dd);
    }
    return __fsub_rn(__fadd_rn(sxx, see[j]), 2.0f * dd);
}

__global__ void __launch_bounds__(NTHREADS, 2) vq_kernel(
        const float* __restrict__ x, const float* __restrict__ e,
        float* __restrict__ out, int n, int ntiles) {
    extern __shared__ __align__(16) char smem[];
    unsigned long long* Eb2 = (unsigned long long*)(smem + OFF_EB);
    float*    sxx_sh = (float*)(smem + OFF_SXX);
    float*    see    = (float*)(smem + OFF_SEE);
    float*    sB     = (float*)(smem + OFF_SB);
    int*      bjsh   = (int*)(smem + OFF_BJ);
    unsigned long long* cmask = (unsigned long long*)(smem + OFF_CM);
    float*    wred   = (float*)(smem + OFF_WRED);

    const int tid = threadIdx.x;
    const int wid = tid >> 5;
    const int lane = tid & 31;
    const int gid = lane >> 2;       // 0..7
    const int tig = lane & 3;        // 0..3

    const float4* x4 = reinterpret_cast<const float4*>(x);
    const float4* e4 = reinterpret_cast<const float4*>(e);
    const uint32_t xs_sa = smem_u32(smem + OFF_XS);

    // ---- ONE-TIME init per CTA: Eb2 pairs (tf32 rna), see exact chain, bounds ----
    for (int idx = tid; idx < 24 * 56 * 4; idx += NTHREADS) {
        const int kq = idx / 224;
        const int rem = idx - kq * 224;
        const int j = rem >> 2, tg = rem & 3;
        uint32_t lo = 0u, hi = 0u;
        if (j < NJ) {
            const int k0 = kq * 8 + tg;
            CVT_TF32(lo, __ldg(e + j * EDIM + k0));
            CVT_TF32(hi, __ldg(e + j * EDIM + k0 + 4));
        }
        Eb2[idx] = ((unsigned long long)hi << 32) | (unsigned long long)lo;
    }
    if (tid < NJP) {
        float s = 1e38f;
        if (tid < NJ) {
            s = 0.f;
            const float* ej = e + (size_t)tid * EDIM;
            #pragma unroll 4
            for (int k = 0; k < EDIM; ++k) { float v = __ldg(ej + k); s = fmaf(v, v, s); }
        }
        see[tid] = s;
        sB[tid] = (tid < NJ) ? 2.4e-3f * sqrtf(s) : 0.f;
    }
    __syncthreads();

    float lsum = 0.f;                // commit-loss partial, accumulated across tiles
    float4* o4 = reinterpret_cast<float4*>(out);

    // ---- persistent tile loop ----
    for (int t = blockIdx.x; t < ntiles; t += gridDim.x) {
        const int tile_base = t * ROWS_PER_BLOCK;

        // stage: 256 threads x 8 granules (16B) per chunk; XOR-swizzled stride-32
        auto stage = [&](int c) {
            const uint32_t dstb = xs_sa + (uint32_t)((c & 1) << 15);
            #pragma unroll
            for (int i = 0; i < 8; ++i) {
                const int idx = tid + i * NTHREADS;
                const int row = idx >> 3, g4 = idx & 7;
                int gr = tile_base + row; if (gr >= n) gr = n - 1;
                cp16(dstb + (uint32_t)(row * 128 + ((g4 ^ (row & 7)) << 4)),
                     x4 + (size_t)gr * 48 + c * 8 + g4);
            }
            CP_COMMIT();
        };

        stage(0);
        stage(1);

        float d2[2][7][4];
        #pragma unroll
        for (int t2 = 0; t2 < 2; ++t2)
            #pragma unroll
            for (int nt = 0; nt < 7; ++nt)
                #pragma unroll
                for (int q = 0; q < 4; ++q) d2[t2][nt][q] = 0.f;
        float s0 = 0.f, s1 = 0.f;    // ||x||^2 partials for row 'tid' (R2 order)

        #pragma unroll 1
        for (int c = 0; c < NCHUNK; ++c) {
            if (c >= NCHUNK - 2) CP_WAIT0(); else CP_WAIT1();
            __syncthreads();                     // chunk c visible to all warps
            const float* xb = (const float*)(smem + OFF_XS + ((c & 1) << 15));

            {                                    // sxx: row 'tid', k ascending
                const float4* xr4 = (const float4*)xb;
                #pragma unroll
                for (int q = 0; q < 8; ++q) {
                    const float4 v = xr4[tid * 8 + (q ^ (tid & 7))];
                    s0 = fmaf(v.x, v.x, s0); s1 = fmaf(v.y, v.y, s1);
                    s0 = fmaf(v.z, v.z, s0); s1 = fmaf(v.w, v.w, s1);
                }
            }
            const int r0 = (wid * 16 + gid) * 32;
            #pragma unroll
            for (int kt = 0; kt < 4; ++kt) {
                const int gsw0 = (((2 * kt)     ^ gid) << 2) + tig;
                const int gsw1 = (((2 * kt + 1) ^ gid) << 2) + tig;
                uint32_t a0, a1, a2, a3, a4, a5, a6, a7;
                CVT_TF32(a0, xb[r0 + gsw0]);            CVT_TF32(a1, xb[r0 + 256 + gsw0]);
                CVT_TF32(a2, xb[r0 + gsw1]);            CVT_TF32(a3, xb[r0 + 256 + gsw1]);
                CVT_TF32(a4, xb[r0 + 4096 + gsw0]);     CVT_TF32(a5, xb[r0 + 4352 + gsw0]);
                CVT_TF32(a6, xb[r0 + 4096 + gsw1]);     CVT_TF32(a7, xb[r0 + 4352 + gsw1]);
                const unsigned long long* ebp =
                    Eb2 + (size_t)((c * 4 + kt) * 56 + gid) * 4 + tig;
                #pragma unroll
                for (int nt = 0; nt < 7; ++nt) {
                    const unsigned long long ev = ebp[nt * 32];   // (k, k+4) pair
                    const uint32_t b0 = (uint32_t)ev;
                    const uint32_t b1 = (uint32_t)(ev >> 32);
                    MMA_TF32(d2[0][nt], a0, a1, a2, a3, b0, b1);
                    MMA_TF32(d2[1][nt], a4, a5, a6, a7, b0, b1);
                }
            }
            __syncthreads();                     // buffer c&1 fully consumed
            if (c + 2 < NCHUNK) stage(c + 2);
        }
        sxx_sh[tid] = s0 + s1;
        __syncthreads();

        // ---- screen: rigorous candidate mask from tf32 dots ----
        #pragma unroll
        for (int t2 = 0; t2 < 2; ++t2)
        #pragma unroll
        for (int half = 0; half < 2; ++half) {
            const int row = t2 * 128 + wid * 16 + gid + half * 8;
            const float sxx = sxx_sh[row];
            const float sqxx = sqrtf(sxx);
            float R = 3.402823466e38f;
            #pragma unroll
            for (int nt = 0; nt < 7; ++nt)
                #pragma unroll
                for (int c2 = 0; c2 < 2; ++c2) {
                    const int j = nt * 8 + 2 * tig + c2;
                    const float dv = d2[t2][nt][half * 2 + c2];
                    const float m = __fsub_rn(__fadd_rn(sxx, see[j]), 2.0f * dv);
                    const float Bv = fmaf(sqxx, sB[j], 3e-4f);
                    R = fminf(R, m + Bv);
                }
            R = fminf(R, __shfl_xor_sync(0xffffffffu, R, 1));
            R = fminf(R, __shfl_xor_sync(0xffffffffu, R, 2));
            unsigned long long lm = 0ull;
            #pragma unroll
            for (int nt = 0; nt < 7; ++nt)
                #pragma unroll
                for (int c2 = 0; c2 < 2; ++c2) {
                    const int j = nt * 8 + 2 * tig + c2;
                    const float dv = d2[t2][nt][half * 2 + c2];
                    const float m = __fsub_rn(__fadd_rn(sxx, see[j]), 2.0f * dv);
                    const float Bv = fmaf(sqxx, sB[j], 3e-4f);
                    if (m - Bv <= R) lm |= 1ull << j;
                }
            lm |= __shfl_xor_sync(0xffffffffu, lm, 1);
            lm |= __shfl_xor_sync(0xffffffffu, lm, 2);
            if (tig == 0) {
                cmask[row] = lm;
                bjsh[row] = (__popcll(lm) == 1) ? (__ffsll(lm) - 1) : -1;
            }
        }
        __syncthreads();

        // ---- rescue: thread per row, exact chain over candidates (ascending j) ----
        {
            const int r = tid;
            int bj = bjsh[r];
            if (bj < 0) {
                int gr = tile_base + r; if (gr >= n) gr = n - 1;
                const float4* xr = x4 + (size_t)gr * 48;
                const float sxx = sxx_sh[r];
                unsigned long long m2 = cmask[r];
                float bv = 3.402823466e38f; bj = 0;
                while (m2) {
                    const int j = __ffsll(m2) - 1; m2 &= m2 - 1;
                    const float m = exact_m(xr, e4, j, sxx, see);
                    if (m < bv) { bv = m; bj = j; }   // ascending j => first-index ties
                }
                bjsh[r] = bj;
            }
            const int grow = tile_base + r;
            if (grow < n) out[(size_t)n * EDIM + grow] = (float)bj;
        }
        __syncthreads();

        // ---- phase 2: coalesced straight-through write + loss ----
        #pragma unroll 4
        for (int it = 0; it < 48; ++it) {             // 32 rows * 48 f4 / 32 lanes
            const int idx = it * 32 + lane;
            const int rl = idx / 48, c4 = idx - rl * 48;
            const int row = (rl >> 4) * 128 + wid * 16 + (rl & 15);
            const int grow = tile_base + row;
            if (grow < n) {
                const int bj = bjsh[row];
                const float4 xq = __ldg(x4 + (size_t)grow * 48 + c4);
                const float4 qq = __ldg(e4 + (size_t)bj * 48 + c4);
                float dx = __fsub_rn(qq.x, xq.x), dy = __fsub_rn(qq.y, xq.y);
                float dz = __fsub_rn(qq.z, xq.z), dw = __fsub_rn(qq.w, xq.w);
                lsum = fmaf(dx, dx, lsum); lsum = fmaf(dy, dy, lsum);
                lsum = fmaf(dz, dz, lsum); lsum = fmaf(dw, dw, lsum);
                float4 o;
                o.x = __fadd_rn(xq.x, dx); o.y = __fadd_rn(xq.y, dy);
                o.z = __fadd_rn(xq.z, dz); o.w = __fadd_rn(xq.w, dw);
                o4[(size_t)grow * 48 + c4] = o;
            }
        }
        // next-tile stage(0) is safe: phase2 reads only GMEM; first inner barrier
        // of the next tile orders any cross-warp smem reuse (bjsh/cmask/sxx).
    }

    // ---- loss reduction + single-kernel finalize ----
    #pragma unroll
    for (int off = 16; off > 0; off >>= 1)
        lsum += __shfl_down_sync(0xffffffffu, lsum, off);
    if (lane == 0) wred[wid] = lsum;
    __syncthreads();
    if (tid == 0) {
        float bs = 0.f;
        #pragma unroll
        for (int w = 0; w < 8; ++w) bs += wred[w];
        atomicAdd(&g_loss_sum, (double)bs);
        __threadfence();
        unsigned int prev = atomicAdd(&g_done, 1u);
        if (prev == gridDim.x - 1) {
            __threadfence();
            double total = atomicAdd(&g_loss_sum, 0.0);
            double mean = total / ((double)n * (double)EDIM);
            out[(size_t)n * EDIM + n]     = (float)(1.25 * mean);  // (1+BETA)*mean
            out[(size_t)n * EDIM + n + 1] = 0.0f;                  // contrastloss
            g_loss_sum = 0.0;
            g_done = 0u;
            __threadfence();
        }
    }
}

extern "C" void kernel_launch(void* const* d_in, const int* in_sizes, int n_in,
                              void* d_out, int out_size) {
    (void)n_in; (void)out_size;
    const float* x = (const float*)d_in[0];   // [N, 192] fp32
    const float* e = (const float*)d_in[1];   // [50, 192] fp32
    float* out = (float*)d_out;               // [N*192 | N | 1 | 1] fp32
    const int n = in_sizes[0] / EDIM;
    const int ntiles = (n + ROWS_PER_BLOCK - 1) / ROWS_PER_BLOCK;

    static int configured = 0;
    if (!configured) {
        cudaFuncSetAttribute(vq_kernel, cudaFuncAttributeMaxDynamicSharedMemorySize,
                             SMEM_TOTAL);
        configured = 1;
    }
    const int grid = ntiles < 296 ? ntiles : 296;   // persistent: 2 CTAs x 148 SMs
    vq_kernel<<<grid, NTHREADS, SMEM_TOTAL>>>(x, e, out, n, ntiles);
}